// round 15
// baseline (speedup 1.0000x reference)
#include <cuda_runtime.h>
#include <cuda_fp16.h>
#include <mma.h>
#include <cstdint>

using namespace nvcuda;

#define BB 4
#define LL 4096
#define DM 1024
#define DI 2048
#define MTOT (BB * LL)          // 16384
#define NCHUNK 16
#define LCH (LL / NCHUNK)       // 256
#define N3 (3 * DI)             // 6144: fused dt|B|C output width

// ---------------------------------------------------------------------------
// Scratch (device globals; allocation is forbidden in kernel_launch)
// ---------------------------------------------------------------------------
__device__ __align__(1024) __half  g_xz  [(size_t)MTOT * (2 * DI)]; // in_proj out
__device__ __align__(1024) __half  g_dtBC[(size_t)MTOT * N3];       // fused proj out
__device__ __align__(1024) __half2 g_hA  [(size_t)MTOT * DI];       // (h_local, Aprefix)

__device__ __align__(1024) __half g_xch[(size_t)MTOT * DI];         // conv out fp16
__device__ __align__(1024) __half g_yh [(size_t)MTOT * DI];         // scan out fp16
__device__ __align__(1024) __half g_xh [(size_t)MTOT * DM];         // x fp16
__device__ __align__(1024) __half g_Wih [(size_t)2 * DI * DM];
__device__ __align__(1024) __half g_Wcat[(size_t)N3 * DI];          // [Wdt;WB;WC]
__device__ __align__(1024) __half g_Woh [(size_t)DM * DI];

__device__ float g_Aprod[BB * NCHUNK * DI];
__device__ float g_Hend [BB * NCHUNK * DI];
__device__ float g_Carry[BB * NCHUNK * DI];

// ---------------------------------------------------------------------------
// helpers
// ---------------------------------------------------------------------------
__device__ __forceinline__ void cp16h(__half* dst, const __half* src) {
    unsigned s = (unsigned)__cvta_generic_to_shared(dst);
    asm volatile("cp.async.cg.shared.global [%0], [%1], 16;" ::"r"(s), "l"(src));
}

// ---------------------------------------------------------------------------
// GEMM: C[M,N] = A[M,K] * W[N,K]^T  (fp16 HMMA m16n16k16, fp32 accumulate)
//   Output type templated: fp32 (final out_proj) or fp16 (intermediates).
//   128x128x64 block, 4 warps (2x2), warp tile 64x64.
//   3-stage cp.async pipeline, 110.6KB smem -> 2 CTAs/SM.
//   SSTH=72 halfs (144B pitch): ldmatrix row banks 36r mod 32 all-distinct.
// ---------------------------------------------------------------------------
#define BM 128
#define BN 128
#define BK 64
#define SSTH 72
#define NSTG 3
#define NTHR 128
#define STAGEH ((BM + BN) * SSTH)                        // halfs per stage
#define GEMM_SMEM (NSTG * STAGEH * (int)sizeof(__half))  // 110592 B

__device__ __forceinline__ void load_stage(__half* sbase, const __half* A,
                                           const __half* W, int kt, int K,
                                           int mBase, int nBase, int tid) {
    const __half* Ab = A + (size_t)mBase * K + (size_t)kt * BK;
    const __half* Wb = W + (size_t)nBase * K + (size_t)kt * BK;
    // (128+128) rows x 64 halfs(128B) = 2048 chunks of 16B; 128 thr -> 16 each
#pragma unroll
    for (int i = 0; i < 16; i++) {
        int chunk = tid + i * NTHR;         // 0..2047
        int tile  = chunk >> 10;            // 0: A, 1: W
        int rem   = chunk & 1023;
        int row   = rem >> 3;               // 0..127
        int col   = (rem & 7) << 3;         // 0,8,...,56 (halfs)
        const __half* src = (tile ? Wb : Ab) + (size_t)row * K + col;
        __half* dst = sbase + tile * (BM * SSTH) + row * SSTH + col;
        cp16h(dst, src);
    }
    asm volatile("cp.async.commit_group;" ::: "memory");
}

template <typename OutT>
__global__ __launch_bounds__(NTHR, 2) void gemm_fp16(const __half* __restrict__ A,
                                                     const __half* __restrict__ W,
                                                     OutT* __restrict__ C,
                                                     int K, int N) {
    extern __shared__ __half smem[];
    const int tid   = threadIdx.x;
    const int warp  = tid >> 5;
    const int wm    = warp & 1;             // 2 warp rows -> 64 M each
    const int wn    = warp >> 1;            // 2 warp cols -> 64 N each
    const int mBase = blockIdx.y * BM;
    const int nBase = blockIdx.x * BN;

    wmma::fragment<wmma::accumulator, 16, 16, 16, float> acc[4][4];
#pragma unroll
    for (int i = 0; i < 4; i++)
#pragma unroll
        for (int j = 0; j < 4; j++) wmma::fill_fragment(acc[i][j], 0.0f);

    const int KT = K / BK;

    // prologue: stages 0 and 1 in flight
    load_stage(smem + 0 * STAGEH, A, W, 0, K, mBase, nBase, tid);
    load_stage(smem + 1 * STAGEH, A, W, 1, K, mBase, nBase, tid);

    for (int kt = 0; kt < KT; kt++) {
        if (kt + 1 < KT) asm volatile("cp.async.wait_group 1;" ::: "memory");
        else             asm volatile("cp.async.wait_group 0;" ::: "memory");
        // barrier: stage kt visible; all warps done with stage kt-1 whose
        // slot (kt+2)%3 is refilled below
        __syncthreads();

        if (kt + 2 < KT)
            load_stage(smem + ((kt + 2) % NSTG) * STAGEH, A, W, kt + 2, K,
                       mBase, nBase, tid);

        const __half* As = smem + (kt % NSTG) * STAGEH;
        const __half* Bs = As + BM * SSTH;

#pragma unroll
        for (int kk = 0; kk < BK / 16; kk++) {
            wmma::fragment<wmma::matrix_a, 16, 16, 16, half, wmma::row_major> af[4];
            wmma::fragment<wmma::matrix_b, 16, 16, 16, half, wmma::col_major> bf[4];
#pragma unroll
            for (int i = 0; i < 4; i++)
                wmma::load_matrix_sync(af[i], As + (wm * 64 + i * 16) * SSTH + kk * 16, SSTH);
#pragma unroll
            for (int j = 0; j < 4; j++)
                wmma::load_matrix_sync(bf[j], Bs + (wn * 64 + j * 16) * SSTH + kk * 16, SSTH);
#pragma unroll
            for (int i = 0; i < 4; i++)
#pragma unroll
                for (int j = 0; j < 4; j++)
                    wmma::mma_sync(acc[i][j], af[i], bf[j], acc[i][j]);
        }
    }

#pragma unroll
    for (int i = 0; i < 4; i++)
#pragma unroll
        for (int j = 0; j < 4; j++) {
            size_t row = (size_t)(mBase + wm * 64 + i * 16);
            int    col = nBase + wn * 64 + j * 16;
            if constexpr (sizeof(OutT) == 2) {
                wmma::fragment<wmma::accumulator, 16, 16, 16, half> hacc;
#pragma unroll
                for (int t = 0; t < hacc.num_elements; t++)
                    hacc.x[t] = __float2half_rn(acc[i][j].x[t]);
                wmma::store_matrix_sync((__half*)C + row * N + col, hacc, N,
                                        wmma::mem_row_major);
            } else {
                wmma::store_matrix_sync((float*)C + row * N + col, acc[i][j], N,
                                        wmma::mem_row_major);
            }
        }
}

// ---------------------------------------------------------------------------
// fp32 -> fp16 producer (8 elements per thread, 16B stores)
// ---------------------------------------------------------------------------
__global__ void to_half_kernel(const float* __restrict__ in,
                               __half* __restrict__ out, size_t n) {
    size_t i = ((size_t)blockIdx.x * blockDim.x + threadIdx.x) * 8;
    if (i >= n) return;
    float4 a = *(const float4*)(in + i);
    float4 b = *(const float4*)(in + i + 4);
    __half2 h[4];
    h[0] = __floats2half2_rn(a.x, a.y);
    h[1] = __floats2half2_rn(a.z, a.w);
    h[2] = __floats2half2_rn(b.x, b.y);
    h[3] = __floats2half2_rn(b.z, b.w);
    *(uint4*)(out + i) = *(uint4*)h;
}

// ---------------------------------------------------------------------------
// depthwise causal conv1d (k=4) + bias + SiLU, 8-wide in d per thread.
// fp16 in (16B vector loads), fp32 math, fp16 out (16B store).
// ---------------------------------------------------------------------------
__global__ void conv_silu_kernel(const __half* __restrict__ xz,
                                 const float* __restrict__ Wc,
                                 const float* __restrict__ bc,
                                 __half* __restrict__ xch) {
    size_t t   = (size_t)blockIdx.x * blockDim.x + threadIdx.x;    // MTOT*DI/8
    if (t >= (size_t)MTOT * DI / 8) return;
    int dv     = (int)(t % (DI / 8));        // d-vector index
    int d0     = dv * 8;
    size_t bl  = t / (DI / 8);               // b*LL + l
    int l      = (int)(bl % LL);

    float acc[8];
#pragma unroll
    for (int k = 0; k < 8; k++) acc[k] = bc[d0 + k];

#pragma unroll
    for (int j = 0; j < 4; j++) {
        int ll = l - 3 + j;
        if (ll >= 0) {
            const __half* src = xz + (bl + (ptrdiff_t)(j - 3)) * (size_t)(2 * DI) + d0;
            uint4 raw = *(const uint4*)src;
            const __half2* hp = (const __half2*)&raw;
#pragma unroll
            for (int p = 0; p < 4; p++) {
                float2 v = __half22float2(hp[p]);
                acc[2 * p]     += Wc[(d0 + 2 * p) * 4 + j]     * v.x;
                acc[2 * p + 1] += Wc[(d0 + 2 * p + 1) * 4 + j] * v.y;
            }
        }
    }

    __half2 outv[4];
#pragma unroll
    for (int p = 0; p < 4; p++) {
        float r0 = acc[2 * p]     * __fdividef(1.0f, 1.0f + __expf(-acc[2 * p]));
        float r1 = acc[2 * p + 1] * __fdividef(1.0f, 1.0f + __expf(-acc[2 * p + 1]));
        outv[p] = __floats2half2_rn(r0, r1);
    }
    *(uint4*)(xch + bl * (size_t)DI + d0) = *(uint4*)outv;
}

// ---------------------------------------------------------------------------
// Chunked SSM scan. Pass 1 stores (h_local, Aprefix) packed fp16x2 — both are
// one-shot roundings of final values (unlike per-step a, these do NOT
// compound). h_t = h_local_t + Aprefix_t * carry  =>  pass 3 is elementwise.
// ---------------------------------------------------------------------------
__device__ __forceinline__ float sp_f(float x) {        // softplus (fast)
    return (x > 20.0f) ? x : __logf(1.0f + __expf(x));
}
__device__ __forceinline__ float sig_f(float x) {
    return __fdividef(1.0f, 1.0f + __expf(-x));
}
__device__ __forceinline__ float tanh_f(float x) {      // exact formula, 1 EX2
    float xc_ = fminf(fmaxf(x, -15.0f), 15.0f);
    float e   = __expf(2.0f * xc_);
    return __fdividef(e - 1.0f, e + 1.0f);
}

__global__ void scan_chunks(const __half* __restrict__ xch,
                            const __half* __restrict__ dtBC,
                            const float* __restrict__ bdt,
                            const float* __restrict__ A_log,
                            __half2* __restrict__ hA,
                            float* __restrict__ Aprod, float* __restrict__ Hend) {
    int idx = blockIdx.x * blockDim.x + threadIdx.x;    // BB*NCHUNK*DI
    if (idx >= BB * NCHUNK * DI) return;
    int d  = idx % DI;
    int bc = idx / DI;
    int c  = bc % NCHUNK;
    int b  = bc / NCHUNK;

    const float bd = bdt[d];
    const float Ad = -expf(A_log[d]);
    int l0 = c * LCH;
    size_t off  = ((size_t)b * LL + l0) * DI + d;             // xch/hA index
    size_t off3 = ((size_t)b * LL + l0) * N3 + d;             // dtBC index

    float uprev = 0.0f;
    if (l0 > 0)
        uprev = __half2float(xch[off - DI]) *
                sig_f(__half2float(dtBC[off3 - N3 + DI]));

    float h = 0.0f, A = 1.0f;
    for (int l = 0; l < LCH; l++) {
        float dtv = sp_f(__half2float(dtBC[off3]) + bd);
        float la  = fminf(fmaxf(Ad * dtv, -10.0f), -0.0001f);
        float a   = __expf(la);
        float u   = __half2float(xch[off]) * sig_f(__half2float(dtBC[off3 + DI]));
        float bta = dtv * 0.5f * (uprev + u);
        h = a * h + bta;
        A *= a;
        uprev = u;
        hA[off] = __floats2half2_rn(h, A);                    // (h_local, Aprefix)
        off  += DI;
        off3 += N3;
    }
    Aprod[idx] = A;
    Hend[idx]  = h;
}

__global__ void scan_carry(const float* __restrict__ Aprod,
                           const float* __restrict__ Hend,
                           float* __restrict__ Carry) {
    int t = blockIdx.x * blockDim.x + threadIdx.x;      // BB*DI
    if (t >= BB * DI) return;
    int d = t % DI, b = t / DI;
    float h = 0.0f;
#pragma unroll
    for (int c = 0; c < NCHUNK; c++) {
        size_t i = ((size_t)b * NCHUNK + c) * DI + d;
        Carry[i] = h;
        h = Aprod[i] * h + Hend[i];
    }
}

// Pass 3: fully elementwise — h = h_local + Aprefix * carry, then gate.
__global__ void scan_out(const __half* __restrict__ xz,
                         const __half* __restrict__ dtBC,
                         const __half2* __restrict__ hA,
                         const float* __restrict__ Carry,
                         __half* __restrict__ yh) {
    size_t idx = (size_t)blockIdx.x * blockDim.x + threadIdx.x;  // MTOT*DI
    if (idx >= (size_t)MTOT * DI) return;
    int d      = (int)(idx % DI);
    size_t bl  = idx / DI;                   // b*LL + l
    int l      = (int)(bl % LL);
    int b      = (int)(bl / LL);
    int c      = l / LCH;

    float carry = Carry[((size_t)b * NCHUNK + c) * DI + d];
    float2 ha   = __half22float2(hA[idx]);
    float h     = ha.x + ha.y * carry;

    float Ct = tanh_f(__half2float(dtBC[bl * (size_t)N3 + 2 * DI + d]));
    float zv = __half2float(xz[bl * (size_t)(2 * DI) + DI + d]);
    float yv = h * Ct * (zv * sig_f(zv));
    yh[idx]  = __float2half_rn(yv);
}

// ---------------------------------------------------------------------------
// Launch
// ---------------------------------------------------------------------------
extern "C" void kernel_launch(void* const* d_in, const int* in_sizes, int n_in,
                              void* d_out, int out_size) {
    const float* x     = (const float*)d_in[0];
    const float* Wi    = (const float*)d_in[1];
    const float* Wconv = (const float*)d_in[2];
    const float* bconv = (const float*)d_in[3];
    const float* Wdt   = (const float*)d_in[4];
    const float* bdt   = (const float*)d_in[5];
    const float* WB    = (const float*)d_in[6];
    const float* WC    = (const float*)d_in[7];
    const float* Wo    = (const float*)d_in[8];
    const float* A_log = (const float*)d_in[9];
    float*       out   = (float*)d_out;

    float *Aprod, *Hend, *Carry;
    __half2 *hA;
    __half *xz, *dtBC, *xh, *xch, *yh, *Wih, *Wcat, *Woh;

    cudaGetSymbolAddress((void**)&xz,    g_xz);
    cudaGetSymbolAddress((void**)&dtBC,  g_dtBC);
    cudaGetSymbolAddress((void**)&hA,    g_hA);
    cudaGetSymbolAddress((void**)&xh,    g_xh);
    cudaGetSymbolAddress((void**)&xch,   g_xch);
    cudaGetSymbolAddress((void**)&yh,    g_yh);
    cudaGetSymbolAddress((void**)&Wih,   g_Wih);
    cudaGetSymbolAddress((void**)&Wcat,  g_Wcat);
    cudaGetSymbolAddress((void**)&Woh,   g_Woh);
    cudaGetSymbolAddress((void**)&Aprod, g_Aprod);
    cudaGetSymbolAddress((void**)&Hend,  g_Hend);
    cudaGetSymbolAddress((void**)&Carry, g_Carry);

    cudaFuncSetAttribute(gemm_fp16<__half>,
                         cudaFuncAttributeMaxDynamicSharedMemorySize, GEMM_SMEM);
    cudaFuncSetAttribute(gemm_fp16<float>,
                         cudaFuncAttributeMaxDynamicSharedMemorySize, GEMM_SMEM);

    const int M = MTOT;

    // 0) fp16 conversion of GEMM operands (Wdt|WB|WC concatenated along N)
    {
        size_t n;
        n = (size_t)M * DM;
        to_half_kernel<<<(unsigned)(n / 8 / 256), 256>>>(x, xh, n);
        n = (size_t)2 * DI * DM;
        to_half_kernel<<<(unsigned)(n / 8 / 256), 256>>>(Wi, Wih, n);
        n = (size_t)DI * DI;
        to_half_kernel<<<(unsigned)(n / 8 / 256), 256>>>(Wdt, Wcat, n);
        to_half_kernel<<<(unsigned)(n / 8 / 256), 256>>>(WB,  Wcat + (size_t)DI * DI, n);
        to_half_kernel<<<(unsigned)(n / 8 / 256), 256>>>(WC,  Wcat + (size_t)2 * DI * DI, n);
        n = (size_t)DM * DI;
        to_half_kernel<<<(unsigned)(n / 8 / 256), 256>>>(Wo, Woh, n);
    }

    // 1) in_proj: xz[M, 4096] (fp16) = xh @ Wih^T
    gemm_fp16<__half><<<dim3((2 * DI) / BN, M / BM), NTHR, GEMM_SMEM>>>(
        xh, Wih, xz, DM, 2 * DI);

    // 2) depthwise causal conv + SiLU -> xch (fp16), 8-wide vectorized
    conv_silu_kernel<<<(unsigned)(((size_t)M * DI / 8) / 256), 256>>>(
        xz, Wconv, bconv, xch);

    // 3) fused dt|B|C projection: dtBC[M, 6144] (fp16) = xch @ Wcat^T
    gemm_fp16<__half><<<dim3(N3 / BN, M / BM), NTHR, GEMM_SMEM>>>(
        xch, Wcat, dtBC, DI, N3);

    // 4) chunked scan: pass1 stores (h_local, Aprefix); tiny carry pass;
    //    pass3 fully elementwise
    scan_chunks<<<(BB * NCHUNK * DI) / 256, 256>>>(xch, dtBC, bdt, A_log,
                                                   hA, Aprod, Hend);
    scan_carry <<<(BB * DI) / 256, 256>>>(Aprod, Hend, Carry);
    scan_out   <<<(unsigned)(((size_t)M * DI) / 256), 256>>>(xz, dtBC, hA,
                                                             Carry, yh);

    // 5) out_proj (fp32 out, final result)
    gemm_fp16<float><<<dim3(DM / BN, M / BM), NTHR, GEMM_SMEM>>>(
        yh, Woh, out, DI, DM);
}

// round 16
// speedup vs baseline: 1.1778x; 1.1778x over previous
#include <cuda_runtime.h>
#include <cuda_fp16.h>
#include <mma.h>
#include <cstdint>

using namespace nvcuda;

#define BB 4
#define LL 4096
#define DM 1024
#define DI 2048
#define MTOT (BB * LL)          // 16384
#define NCHUNK 16
#define LCH (LL / NCHUNK)       // 256
#define N3 (3 * DI)             // 6144: fused dt|B|C output width

// ---------------------------------------------------------------------------
// Scratch (device globals; allocation is forbidden in kernel_launch)
// ---------------------------------------------------------------------------
__device__ __align__(1024) __half g_xz  [(size_t)MTOT * (2 * DI)]; // in_proj out (fp16)
__device__ __align__(1024) __half g_dtBC[(size_t)MTOT * N3];       // fused proj out (fp16)
__device__ __align__(1024) float  g_a   [(size_t)MTOT * DI];       // decay coeff (fp32)
__device__ __align__(1024) __half g_beta[(size_t)MTOT * DI];       // input term (fp16)

__device__ __align__(1024) __half g_xch[(size_t)MTOT * DI];        // conv out fp16
__device__ __align__(1024) __half g_yh [(size_t)MTOT * DI];        // scan out fp16
__device__ __align__(1024) __half g_xh [(size_t)MTOT * DM];        // x fp16
__device__ __align__(1024) __half g_Wih [(size_t)2 * DI * DM];
__device__ __align__(1024) __half g_Wcat[(size_t)N3 * DI];         // [Wdt;WB;WC]
__device__ __align__(1024) __half g_Woh [(size_t)DM * DI];

__device__ float g_Aprod[BB * NCHUNK * DI];
__device__ float g_Hend [BB * NCHUNK * DI];
__device__ float g_Carry[BB * NCHUNK * DI];

// ---------------------------------------------------------------------------
// helpers
// ---------------------------------------------------------------------------
__device__ __forceinline__ void cp16h(__half* dst, const __half* src) {
    unsigned s = (unsigned)__cvta_generic_to_shared(dst);
    asm volatile("cp.async.cg.shared.global [%0], [%1], 16;" ::"r"(s), "l"(src));
}

// ---------------------------------------------------------------------------
// GEMM: C[M,N] = A[M,K] * W[N,K]^T  (fp16 HMMA m16n16k16, fp32 accumulate)
//   Output type templated: fp32 (final out_proj) or fp16 (intermediates).
//   128x128x64 block, 4 warps (2x2), warp tile 64x64.
//   3-stage cp.async pipeline, 110.6KB smem -> 2 CTAs/SM.
//   SSTH=72 halfs (144B pitch): ldmatrix row banks 36r mod 32 all-distinct.
// ---------------------------------------------------------------------------
#define BM 128
#define BN 128
#define BK 64
#define SSTH 72
#define NSTG 3
#define NTHR 128
#define STAGEH ((BM + BN) * SSTH)                        // halfs per stage
#define GEMM_SMEM (NSTG * STAGEH * (int)sizeof(__half))  // 110592 B

__device__ __forceinline__ void load_stage(__half* sbase, const __half* A,
                                           const __half* W, int kt, int K,
                                           int mBase, int nBase, int tid) {
    const __half* Ab = A + (size_t)mBase * K + (size_t)kt * BK;
    const __half* Wb = W + (size_t)nBase * K + (size_t)kt * BK;
    // (128+128) rows x 64 halfs(128B) = 2048 chunks of 16B; 128 thr -> 16 each
#pragma unroll
    for (int i = 0; i < 16; i++) {
        int chunk = tid + i * NTHR;         // 0..2047
        int tile  = chunk >> 10;            // 0: A, 1: W
        int rem   = chunk & 1023;
        int row   = rem >> 3;               // 0..127
        int col   = (rem & 7) << 3;         // 0,8,...,56 (halfs)
        const __half* src = (tile ? Wb : Ab) + (size_t)row * K + col;
        __half* dst = sbase + tile * (BM * SSTH) + row * SSTH + col;
        cp16h(dst, src);
    }
    asm volatile("cp.async.commit_group;" ::: "memory");
}

template <typename OutT>
__global__ __launch_bounds__(NTHR, 2) void gemm_fp16(const __half* __restrict__ A,
                                                     const __half* __restrict__ W,
                                                     OutT* __restrict__ C,
                                                     int K, int N) {
    extern __shared__ __half smem[];
    const int tid   = threadIdx.x;
    const int warp  = tid >> 5;
    const int wm    = warp & 1;             // 2 warp rows -> 64 M each
    const int wn    = warp >> 1;            // 2 warp cols -> 64 N each
    const int mBase = blockIdx.y * BM;
    const int nBase = blockIdx.x * BN;

    wmma::fragment<wmma::accumulator, 16, 16, 16, float> acc[4][4];
#pragma unroll
    for (int i = 0; i < 4; i++)
#pragma unroll
        for (int j = 0; j < 4; j++) wmma::fill_fragment(acc[i][j], 0.0f);

    const int KT = K / BK;

    // prologue: stages 0 and 1 in flight
    load_stage(smem + 0 * STAGEH, A, W, 0, K, mBase, nBase, tid);
    load_stage(smem + 1 * STAGEH, A, W, 1, K, mBase, nBase, tid);

    for (int kt = 0; kt < KT; kt++) {
        if (kt + 1 < KT) asm volatile("cp.async.wait_group 1;" ::: "memory");
        else             asm volatile("cp.async.wait_group 0;" ::: "memory");
        // barrier: stage kt visible; all warps done with stage kt-1 whose
        // slot (kt+2)%3 is refilled below
        __syncthreads();

        if (kt + 2 < KT)
            load_stage(smem + ((kt + 2) % NSTG) * STAGEH, A, W, kt + 2, K,
                       mBase, nBase, tid);

        const __half* As = smem + (kt % NSTG) * STAGEH;
        const __half* Bs = As + BM * SSTH;

#pragma unroll
        for (int kk = 0; kk < BK / 16; kk++) {
            wmma::fragment<wmma::matrix_a, 16, 16, 16, half, wmma::row_major> af[4];
            wmma::fragment<wmma::matrix_b, 16, 16, 16, half, wmma::col_major> bf[4];
#pragma unroll
            for (int i = 0; i < 4; i++)
                wmma::load_matrix_sync(af[i], As + (wm * 64 + i * 16) * SSTH + kk * 16, SSTH);
#pragma unroll
            for (int j = 0; j < 4; j++)
                wmma::load_matrix_sync(bf[j], Bs + (wn * 64 + j * 16) * SSTH + kk * 16, SSTH);
#pragma unroll
            for (int i = 0; i < 4; i++)
#pragma unroll
                for (int j = 0; j < 4; j++)
                    wmma::mma_sync(acc[i][j], af[i], bf[j], acc[i][j]);
        }
    }

#pragma unroll
    for (int i = 0; i < 4; i++)
#pragma unroll
        for (int j = 0; j < 4; j++) {
            size_t row = (size_t)(mBase + wm * 64 + i * 16);
            int    col = nBase + wn * 64 + j * 16;
            if constexpr (sizeof(OutT) == 2) {
                wmma::fragment<wmma::accumulator, 16, 16, 16, half> hacc;
#pragma unroll
                for (int t = 0; t < hacc.num_elements; t++)
                    hacc.x[t] = __float2half_rn(acc[i][j].x[t]);
                wmma::store_matrix_sync((__half*)C + row * N + col, hacc, N,
                                        wmma::mem_row_major);
            } else {
                wmma::store_matrix_sync((float*)C + row * N + col, acc[i][j], N,
                                        wmma::mem_row_major);
            }
        }
}

// ---------------------------------------------------------------------------
// Fused fp32 -> fp16 producer: one launch, 6 segments (8 elems per thread).
// ---------------------------------------------------------------------------
struct SegTable {
    const float* src[6];
    __half*      dst[6];
    size_t       cum[7];   // cumulative element counts, cum[0]=0
};

__global__ void to_half_multi(SegTable st) {
    size_t i8 = ((size_t)blockIdx.x * blockDim.x + threadIdx.x) * 8;
    if (i8 >= st.cum[6]) return;
    int s = 0;
#pragma unroll
    for (int k = 1; k < 6; k++) s += (i8 >= st.cum[k]);
    size_t off = i8 - st.cum[s];
    const float* in  = st.src[s] + off;
    __half*      out = st.dst[s] + off;
    float4 a = *(const float4*)(in);
    float4 b = *(const float4*)(in + 4);
    __half2 h[4];
    h[0] = __floats2half2_rn(a.x, a.y);
    h[1] = __floats2half2_rn(a.z, a.w);
    h[2] = __floats2half2_rn(b.x, b.y);
    h[3] = __floats2half2_rn(b.z, b.w);
    *(uint4*)out = *(uint4*)h;
}

// ---------------------------------------------------------------------------
// depthwise causal conv1d (k=4) + bias + SiLU; fp16 in, fp32 math, fp16 out
// ---------------------------------------------------------------------------
__global__ void conv_silu_kernel(const __half* __restrict__ xz,
                                 const float* __restrict__ Wc,
                                 const float* __restrict__ bc,
                                 __half* __restrict__ xch) {
    size_t idx = (size_t)blockIdx.x * blockDim.x + threadIdx.x;
    if (idx >= (size_t)MTOT * DI) return;
    int d     = (int)(idx % DI);
    size_t bl = idx / DI;
    int l     = (int)(bl % LL);

    const __half* xp = xz + bl * (size_t)(2 * DI) + d;
    float acc = bc[d];
#pragma unroll
    for (int j = 0; j < 4; j++) {
        int ll = l - 3 + j;
        if (ll >= 0)
            acc += Wc[d * 4 + j] * __half2float(xp[(ptrdiff_t)(j - 3) * (2 * DI)]);
    }
    float r = acc * __fdividef(1.0f, 1.0f + __expf(-acc));
    xch[idx] = __float2half_rn(r);
}

// ---------------------------------------------------------------------------
// Chunked SSM scan (3 passes). Pass 1 stores a (fp32 — errors would compound
// over the scan's long memory) and beta (fp16 — one-shot roundable);
// pass 3 replays h = a*h + beta and applies the output gate.
// ---------------------------------------------------------------------------
__device__ __forceinline__ float sp_f(float x) {        // softplus (fast)
    return (x > 20.0f) ? x : __logf(1.0f + __expf(x));
}
__device__ __forceinline__ float sig_f(float x) {
    return __fdividef(1.0f, 1.0f + __expf(-x));
}
__device__ __forceinline__ float tanh_f(float x) {      // exact formula, 1 EX2
    float xc_ = fminf(fmaxf(x, -15.0f), 15.0f);
    float e   = __expf(2.0f * xc_);
    return __fdividef(e - 1.0f, e + 1.0f);
}

__global__ void scan_chunks(const __half* __restrict__ xch,
                            const __half* __restrict__ dtBC,
                            const float* __restrict__ bdt,
                            const float* __restrict__ A_log,
                            float* __restrict__ a_arr,
                            __half* __restrict__ beta_arr,
                            float* __restrict__ Aprod, float* __restrict__ Hend) {
    int idx = blockIdx.x * blockDim.x + threadIdx.x;    // BB*NCHUNK*DI
    if (idx >= BB * NCHUNK * DI) return;
    int d  = idx % DI;
    int bc = idx / DI;
    int c  = bc % NCHUNK;
    int b  = bc / NCHUNK;

    const float bd = bdt[d];
    const float Ad = -expf(A_log[d]);
    int l0 = c * LCH;
    size_t off  = ((size_t)b * LL + l0) * DI + d;             // xch/a/beta index
    size_t off3 = ((size_t)b * LL + l0) * N3 + d;             // dtBC index

    float uprev = 0.0f;
    if (l0 > 0)
        uprev = __half2float(xch[off - DI]) *
                sig_f(__half2float(dtBC[off3 - N3 + DI]));

    float h = 0.0f, A = 1.0f;
    for (int l = 0; l < LCH; l++) {
        float dtv = sp_f(__half2float(dtBC[off3]) + bd);
        float la  = fminf(fmaxf(Ad * dtv, -10.0f), -0.0001f);
        float a   = __expf(la);
        float u   = __half2float(xch[off]) * sig_f(__half2float(dtBC[off3 + DI]));
        float bta = dtv * 0.5f * (uprev + u);
        h = a * h + bta;
        A *= a;
        uprev = u;
        a_arr[off]    = a;
        beta_arr[off] = __float2half_rn(bta);
        off  += DI;
        off3 += N3;
    }
    Aprod[idx] = A;
    Hend[idx]  = h;
}

__global__ void scan_carry(const float* __restrict__ Aprod,
                           const float* __restrict__ Hend,
                           float* __restrict__ Carry) {
    int t = blockIdx.x * blockDim.x + threadIdx.x;      // BB*DI
    if (t >= BB * DI) return;
    int d = t % DI, b = t / DI;
    float h = 0.0f;
#pragma unroll
    for (int c = 0; c < NCHUNK; c++) {
        size_t i = ((size_t)b * NCHUNK + c) * DI + d;
        Carry[i] = h;
        h = Aprod[i] * h + Hend[i];
    }
}

__global__ void scan_out(const __half* __restrict__ xz,
                         const __half* __restrict__ dtBC,
                         const float* __restrict__ a_arr,
                         const __half* __restrict__ beta_arr,
                         const float* __restrict__ Carry,
                         __half* __restrict__ yh) {
    int idx = blockIdx.x * blockDim.x + threadIdx.x;
    if (idx >= BB * NCHUNK * DI) return;
    int d  = idx % DI;
    int bc = idx / DI;
    int c  = bc % NCHUNK;
    int b  = bc / NCHUNK;

    int l0 = c * LCH;
    size_t off  = ((size_t)b * LL + l0) * DI + d;
    size_t off3 = ((size_t)b * LL + l0) * N3 + 2 * DI + d;    // C-proj column
    size_t zoff = ((size_t)b * LL + l0) * (size_t)(2 * DI) + DI + d;

    float h = Carry[idx];
    for (int l = 0; l < LCH; l++) {
        h = a_arr[off] * h + __half2float(beta_arr[off]);

        float Ct = tanh_f(__half2float(dtBC[off3]));
        float zv = __half2float(xz[zoff]);
        float yv = h * Ct * (zv * sig_f(zv));
        yh[off]  = __float2half_rn(yv);

        off  += DI;
        off3 += N3;
        zoff += 2 * DI;
    }
}

// ---------------------------------------------------------------------------
// Launch
// ---------------------------------------------------------------------------
extern "C" void kernel_launch(void* const* d_in, const int* in_sizes, int n_in,
                              void* d_out, int out_size) {
    const float* x     = (const float*)d_in[0];
    const float* Wi    = (const float*)d_in[1];
    const float* Wconv = (const float*)d_in[2];
    const float* bconv = (const float*)d_in[3];
    const float* Wdt   = (const float*)d_in[4];
    const float* bdt   = (const float*)d_in[5];
    const float* WB    = (const float*)d_in[6];
    const float* WC    = (const float*)d_in[7];
    const float* Wo    = (const float*)d_in[8];
    const float* A_log = (const float*)d_in[9];
    float*       out   = (float*)d_out;

    float *a_arr, *Aprod, *Hend, *Carry;
    __half *beta_arr;
    __half *xz, *dtBC, *xh, *xch, *yh, *Wih, *Wcat, *Woh;

    cudaGetSymbolAddress((void**)&xz,    g_xz);
    cudaGetSymbolAddress((void**)&dtBC,  g_dtBC);
    cudaGetSymbolAddress((void**)&a_arr, g_a);
    cudaGetSymbolAddress((void**)&beta_arr, g_beta);
    cudaGetSymbolAddress((void**)&xh,    g_xh);
    cudaGetSymbolAddress((void**)&xch,   g_xch);
    cudaGetSymbolAddress((void**)&yh,    g_yh);
    cudaGetSymbolAddress((void**)&Wih,   g_Wih);
    cudaGetSymbolAddress((void**)&Wcat,  g_Wcat);
    cudaGetSymbolAddress((void**)&Woh,   g_Woh);
    cudaGetSymbolAddress((void**)&Aprod, g_Aprod);
    cudaGetSymbolAddress((void**)&Hend,  g_Hend);
    cudaGetSymbolAddress((void**)&Carry, g_Carry);

    cudaFuncSetAttribute(gemm_fp16<__half>,
                         cudaFuncAttributeMaxDynamicSharedMemorySize, GEMM_SMEM);
    cudaFuncSetAttribute(gemm_fp16<float>,
                         cudaFuncAttributeMaxDynamicSharedMemorySize, GEMM_SMEM);

    const int M = MTOT;

    // 0) fp16 conversion of all GEMM operands in ONE launch
    {
        SegTable st;
        size_t n0 = (size_t)M * DM;        // x
        size_t n1 = (size_t)2 * DI * DM;   // Wi
        size_t n2 = (size_t)DI * DI;       // Wdt
        size_t n3 = (size_t)DI * DI;       // WB
        size_t n4 = (size_t)DI * DI;       // WC
        size_t n5 = (size_t)DM * DI;       // Wo
        st.src[0] = x;    st.dst[0] = xh;
        st.src[1] = Wi;   st.dst[1] = Wih;
        st.src[2] = Wdt;  st.dst[2] = Wcat;
        st.src[3] = WB;   st.dst[3] = Wcat + n2;
        st.src[4] = WC;   st.dst[4] = Wcat + 2 * n2;
        st.src[5] = Wo;   st.dst[5] = Woh;
        st.cum[0] = 0;
        st.cum[1] = st.cum[0] + n0;
        st.cum[2] = st.cum[1] + n1;
        st.cum[3] = st.cum[2] + n2;
        st.cum[4] = st.cum[3] + n3;
        st.cum[5] = st.cum[4] + n4;
        st.cum[6] = st.cum[5] + n5;
        unsigned blocks = (unsigned)((st.cum[6] / 8 + 255) / 256);
        to_half_multi<<<blocks, 256>>>(st);
    }

    // 1) in_proj: xz[M, 4096] (fp16) = xh @ Wih^T
    gemm_fp16<__half><<<dim3((2 * DI) / BN, M / BM), NTHR, GEMM_SMEM>>>(
        xh, Wih, xz, DM, 2 * DI);

    // 2) depthwise causal conv + SiLU -> xch (fp16)
    conv_silu_kernel<<<(unsigned)(((size_t)M * DI) / 256), 256>>>(xz, Wconv, bconv, xch);

    // 3) fused dt|B|C projection: dtBC[M, 6144] (fp16) = xch @ Wcat^T
    gemm_fp16<__half><<<dim3(N3 / BN, M / BM), NTHR, GEMM_SMEM>>>(
        xch, Wcat, dtBC, DI, N3);

    // 4) chunked scan (3 passes; a fp32, beta fp16)
    scan_chunks<<<(BB * NCHUNK * DI) / 256, 256>>>(xch, dtBC, bdt, A_log,
                                                   a_arr, beta_arr, Aprod, Hend);
    scan_carry <<<(BB * DI) / 256, 256>>>(Aprod, Hend, Carry);
    scan_out   <<<(BB * NCHUNK * DI) / 256, 256>>>(xz, dtBC, a_arr, beta_arr,
                                                   Carry, yh);

    // 5) out_proj (fp32 out, final result)
    gemm_fp16<float><<<dim3(DM / BN, M / BM), NTHR, GEMM_SMEM>>>(
        yh, Woh, out, DI, DM);
}

// round 17
// speedup vs baseline: 1.1793x; 1.0012x over previous
#include <cuda_runtime.h>
#include <cuda_fp16.h>
#include <mma.h>
#include <cstdint>

using namespace nvcuda;

#define BB 4
#define LL 4096
#define DM 1024
#define DI 2048
#define MTOT (BB * LL)          // 16384
#define NCHUNK 16
#define LCH (LL / NCHUNK)       // 256
#define N3 (3 * DI)             // 6144: fused dt|B|C output width

// ---------------------------------------------------------------------------
// Scratch (device globals; allocation is forbidden in kernel_launch)
// ---------------------------------------------------------------------------
__device__ __align__(1024) __half  g_xz  [(size_t)MTOT * (2 * DI)]; // in_proj out
__device__ __align__(1024) __half  g_dtBC[(size_t)MTOT * N3];       // fused proj out
__device__ __align__(1024) __half2 g_hA  [(size_t)MTOT * DI];       // (h_local, Aprefix)

__device__ __align__(1024) __half g_xch[(size_t)MTOT * DI];         // conv out fp16
__device__ __align__(1024) __half g_yh [(size_t)MTOT * DI];         // scan out fp16
__device__ __align__(1024) __half g_xh [(size_t)MTOT * DM];         // x fp16
__device__ __align__(1024) __half g_Wih [(size_t)2 * DI * DM];
__device__ __align__(1024) __half g_Wcat[(size_t)N3 * DI];          // [Wdt;WB;WC]
__device__ __align__(1024) __half g_Woh [(size_t)DM * DI];

__device__ float g_Aprod[BB * NCHUNK * DI];
__device__ float g_Hend [BB * NCHUNK * DI];
__device__ float g_Carry[BB * NCHUNK * DI];

// ---------------------------------------------------------------------------
// helpers
// ---------------------------------------------------------------------------
__device__ __forceinline__ void cp16h(__half* dst, const __half* src) {
    unsigned s = (unsigned)__cvta_generic_to_shared(dst);
    asm volatile("cp.async.cg.shared.global [%0], [%1], 16;" ::"r"(s), "l"(src));
}

// ---------------------------------------------------------------------------
// GEMM: C[M,N] = A[M,K] * W[N,K]^T  (fp16 HMMA m16n16k16, fp32 accumulate)
//   Output type templated: fp32 (final out_proj) or fp16 (intermediates).
//   128x128x64 block, 4 warps (2x2), warp tile 64x64.
//   3-stage cp.async pipeline, 110.6KB smem -> 2 CTAs/SM.
//   SSTH=72 halfs (144B pitch): ldmatrix row banks 36r mod 32 all-distinct.
//   (R16-proven config; per-SMSP model shows it at the practical wmma ceiling.)
// ---------------------------------------------------------------------------
#define BM 128
#define BN 128
#define BK 64
#define SSTH 72
#define NSTG 3
#define NTHR 128
#define STAGEH ((BM + BN) * SSTH)                        // halfs per stage
#define GEMM_SMEM (NSTG * STAGEH * (int)sizeof(__half))  // 110592 B

__device__ __forceinline__ void load_stage(__half* sbase, const __half* A,
                                           const __half* W, int kt, int K,
                                           int mBase, int nBase, int tid) {
    const __half* Ab = A + (size_t)mBase * K + (size_t)kt * BK;
    const __half* Wb = W + (size_t)nBase * K + (size_t)kt * BK;
    // (128+128) rows x 64 halfs(128B) = 2048 chunks of 16B; 128 thr -> 16 each
#pragma unroll
    for (int i = 0; i < 16; i++) {
        int chunk = tid + i * NTHR;         // 0..2047
        int tile  = chunk >> 10;            // 0: A, 1: W
        int rem   = chunk & 1023;
        int row   = rem >> 3;               // 0..127
        int col   = (rem & 7) << 3;         // 0,8,...,56 (halfs)
        const __half* src = (tile ? Wb : Ab) + (size_t)row * K + col;
        __half* dst = sbase + tile * (BM * SSTH) + row * SSTH + col;
        cp16h(dst, src);
    }
    asm volatile("cp.async.commit_group;" ::: "memory");
}

template <typename OutT>
__global__ __launch_bounds__(NTHR, 2) void gemm_fp16(const __half* __restrict__ A,
                                                     const __half* __restrict__ W,
                                                     OutT* __restrict__ C,
                                                     int K, int N) {
    extern __shared__ __half smem[];
    const int tid   = threadIdx.x;
    const int warp  = tid >> 5;
    const int wm    = warp & 1;             // 2 warp rows -> 64 M each
    const int wn    = warp >> 1;            // 2 warp cols -> 64 N each
    const int mBase = blockIdx.y * BM;
    const int nBase = blockIdx.x * BN;

    wmma::fragment<wmma::accumulator, 16, 16, 16, float> acc[4][4];
#pragma unroll
    for (int i = 0; i < 4; i++)
#pragma unroll
        for (int j = 0; j < 4; j++) wmma::fill_fragment(acc[i][j], 0.0f);

    const int KT = K / BK;

    // prologue: stages 0 and 1 in flight
    load_stage(smem + 0 * STAGEH, A, W, 0, K, mBase, nBase, tid);
    load_stage(smem + 1 * STAGEH, A, W, 1, K, mBase, nBase, tid);

    for (int kt = 0; kt < KT; kt++) {
        if (kt + 1 < KT) asm volatile("cp.async.wait_group 1;" ::: "memory");
        else             asm volatile("cp.async.wait_group 0;" ::: "memory");
        // barrier: stage kt visible; all warps done with stage kt-1 whose
        // slot (kt+2)%3 is refilled below
        __syncthreads();

        if (kt + 2 < KT)
            load_stage(smem + ((kt + 2) % NSTG) * STAGEH, A, W, kt + 2, K,
                       mBase, nBase, tid);

        const __half* As = smem + (kt % NSTG) * STAGEH;
        const __half* Bs = As + BM * SSTH;

#pragma unroll
        for (int kk = 0; kk < BK / 16; kk++) {
            wmma::fragment<wmma::matrix_a, 16, 16, 16, half, wmma::row_major> af[4];
            wmma::fragment<wmma::matrix_b, 16, 16, 16, half, wmma::col_major> bf[4];
#pragma unroll
            for (int i = 0; i < 4; i++)
                wmma::load_matrix_sync(af[i], As + (wm * 64 + i * 16) * SSTH + kk * 16, SSTH);
#pragma unroll
            for (int j = 0; j < 4; j++)
                wmma::load_matrix_sync(bf[j], Bs + (wn * 64 + j * 16) * SSTH + kk * 16, SSTH);
#pragma unroll
            for (int i = 0; i < 4; i++)
#pragma unroll
                for (int j = 0; j < 4; j++)
                    wmma::mma_sync(acc[i][j], af[i], bf[j], acc[i][j]);
        }
    }

#pragma unroll
    for (int i = 0; i < 4; i++)
#pragma unroll
        for (int j = 0; j < 4; j++) {
            size_t row = (size_t)(mBase + wm * 64 + i * 16);
            int    col = nBase + wn * 64 + j * 16;
            if constexpr (sizeof(OutT) == 2) {
                wmma::fragment<wmma::accumulator, 16, 16, 16, half> hacc;
#pragma unroll
                for (int t = 0; t < hacc.num_elements; t++)
                    hacc.x[t] = __float2half_rn(acc[i][j].x[t]);
                wmma::store_matrix_sync((__half*)C + row * N + col, hacc, N,
                                        wmma::mem_row_major);
            } else {
                wmma::store_matrix_sync((float*)C + row * N + col, acc[i][j], N,
                                        wmma::mem_row_major);
            }
        }
}

// ---------------------------------------------------------------------------
// Fused fp32 -> fp16 producer: one launch, 6 segments (8 elems per thread).
// ---------------------------------------------------------------------------
struct SegTable {
    const float* src[6];
    __half*      dst[6];
    size_t       cum[7];   // cumulative element counts, cum[0]=0
};

__global__ void to_half_multi(SegTable st) {
    size_t i8 = ((size_t)blockIdx.x * blockDim.x + threadIdx.x) * 8;
    if (i8 >= st.cum[6]) return;
    int s = 0;
#pragma unroll
    for (int k = 1; k < 6; k++) s += (i8 >= st.cum[k]);
    size_t off = i8 - st.cum[s];
    const float* in  = st.src[s] + off;
    __half*      out = st.dst[s] + off;
    float4 a = *(const float4*)(in);
    float4 b = *(const float4*)(in + 4);
    __half2 h[4];
    h[0] = __floats2half2_rn(a.x, a.y);
    h[1] = __floats2half2_rn(a.z, a.w);
    h[2] = __floats2half2_rn(b.x, b.y);
    h[3] = __floats2half2_rn(b.z, b.w);
    *(uint4*)out = *(uint4*)h;
}

// ---------------------------------------------------------------------------
// depthwise causal conv1d (k=4) + bias + SiLU; fp16 in, fp32 math, fp16 out
// (scalar version — proven in R14/R16; the vectorized variant is the other
//  R15 suspect and stays out for attribution)
// ---------------------------------------------------------------------------
__global__ void conv_silu_kernel(const __half* __restrict__ xz,
                                 const float* __restrict__ Wc,
                                 const float* __restrict__ bc,
                                 __half* __restrict__ xch) {
    size_t idx = (size_t)blockIdx.x * blockDim.x + threadIdx.x;
    if (idx >= (size_t)MTOT * DI) return;
    int d     = (int)(idx % DI);
    size_t bl = idx / DI;
    int l     = (int)(bl % LL);

    const __half* xp = xz + bl * (size_t)(2 * DI) + d;
    float acc = bc[d];
#pragma unroll
    for (int j = 0; j < 4; j++) {
        int ll = l - 3 + j;
        if (ll >= 0)
            acc += Wc[d * 4 + j] * __half2float(xp[(ptrdiff_t)(j - 3) * (2 * DI)]);
    }
    float r = acc * __fdividef(1.0f, 1.0f + __expf(-acc));
    xch[idx] = __float2half_rn(r);
}

// ---------------------------------------------------------------------------
// Chunked SSM scan. Pass 1 stores (h_local, Aprefix) packed fp16x2 — both
// one-shot roundings of FINAL values (unlike per-step a whose error would
// compound). h_t = h_local_t + Aprefix_t * carry  =>  pass 3 is elementwise.
// fp16 Aprefix underflow (<6e-8) is exactly where the carry term is
// genuinely negligible.
// ---------------------------------------------------------------------------
__device__ __forceinline__ float sp_f(float x) {        // softplus (fast)
    return (x > 20.0f) ? x : __logf(1.0f + __expf(x));
}
__device__ __forceinline__ float sig_f(float x) {
    return __fdividef(1.0f, 1.0f + __expf(-x));
}
__device__ __forceinline__ float tanh_f(float x) {      // exact formula, 1 EX2
    float xc_ = fminf(fmaxf(x, -15.0f), 15.0f);
    float e   = __expf(2.0f * xc_);
    return __fdividef(e - 1.0f, e + 1.0f);
}

__global__ void scan_chunks(const __half* __restrict__ xch,
                            const __half* __restrict__ dtBC,
                            const float* __restrict__ bdt,
                            const float* __restrict__ A_log,
                            __half2* __restrict__ hA,
                            float* __restrict__ Aprod, float* __restrict__ Hend) {
    int idx = blockIdx.x * blockDim.x + threadIdx.x;    // BB*NCHUNK*DI
    if (idx >= BB * NCHUNK * DI) return;
    int d  = idx % DI;
    int bc = idx / DI;
    int c  = bc % NCHUNK;
    int b  = bc / NCHUNK;

    const float bd = bdt[d];
    const float Ad = -expf(A_log[d]);
    int l0 = c * LCH;
    size_t off  = ((size_t)b * LL + l0) * DI + d;             // xch/hA index
    size_t off3 = ((size_t)b * LL + l0) * N3 + d;             // dtBC index

    float uprev = 0.0f;
    if (l0 > 0)
        uprev = __half2float(xch[off - DI]) *
                sig_f(__half2float(dtBC[off3 - N3 + DI]));

    float h = 0.0f, A = 1.0f;
    for (int l = 0; l < LCH; l++) {
        float dtv = sp_f(__half2float(dtBC[off3]) + bd);
        float la  = fminf(fmaxf(Ad * dtv, -10.0f), -0.0001f);
        float a   = __expf(la);
        float u   = __half2float(xch[off]) * sig_f(__half2float(dtBC[off3 + DI]));
        float bta = dtv * 0.5f * (uprev + u);
        h = a * h + bta;
        A *= a;
        uprev = u;
        hA[off] = __floats2half2_rn(h, A);                    // one-shot rounds
        off  += DI;
        off3 += N3;
    }
    Aprod[idx] = A;
    Hend[idx]  = h;
}

__global__ void scan_carry(const float* __restrict__ Aprod,
                           const float* __restrict__ Hend,
                           float* __restrict__ Carry) {
    int t = blockIdx.x * blockDim.x + threadIdx.x;      // BB*DI
    if (t >= BB * DI) return;
    int d = t % DI, b = t / DI;
    float h = 0.0f;
#pragma unroll
    for (int c = 0; c < NCHUNK; c++) {
        size_t i = ((size_t)b * NCHUNK + c) * DI + d;
        Carry[i] = h;
        h = Aprod[i] * h + Hend[i];
    }
}

// Pass 3: fully elementwise — h = h_local + Aprefix * carry, then gate.
__global__ void scan_out(const __half* __restrict__ xz,
                         const __half* __restrict__ dtBC,
                         const __half2* __restrict__ hA,
                         const float* __restrict__ Carry,
                         __half* __restrict__ yh) {
    size_t idx = (size_t)blockIdx.x * blockDim.x + threadIdx.x;  // MTOT*DI
    if (idx >= (size_t)MTOT * DI) return;
    int d      = (int)(idx % DI);
    size_t bl  = idx / DI;                   // b*LL + l
    int l      = (int)(bl % LL);
    int b      = (int)(bl / LL);
    int c      = l / LCH;

    float carry = Carry[((size_t)b * NCHUNK + c) * DI + d];
    float2 ha   = __half22float2(hA[idx]);
    float h     = ha.x + ha.y * carry;

    float Ct = tanh_f(__half2float(dtBC[bl * (size_t)N3 + 2 * DI + d]));
    float zv = __half2float(xz[bl * (size_t)(2 * DI) + DI + d]);
    float yv = h * Ct * (zv * sig_f(zv));
    yh[idx]  = __float2half_rn(yv);
}

// ---------------------------------------------------------------------------
// Launch
// ---------------------------------------------------------------------------
extern "C" void kernel_launch(void* const* d_in, const int* in_sizes, int n_in,
                              void* d_out, int out_size) {
    const float* x     = (const float*)d_in[0];
    const float* Wi    = (const float*)d_in[1];
    const float* Wconv = (const float*)d_in[2];
    const float* bconv = (const float*)d_in[3];
    const float* Wdt   = (const float*)d_in[4];
    const float* bdt   = (const float*)d_in[5];
    const float* WB    = (const float*)d_in[6];
    const float* WC    = (const float*)d_in[7];
    const float* Wo    = (const float*)d_in[8];
    const float* A_log = (const float*)d_in[9];
    float*       out   = (float*)d_out;

    float *Aprod, *Hend, *Carry;
    __half2 *hA;
    __half *xz, *dtBC, *xh, *xch, *yh, *Wih, *Wcat, *Woh;

    cudaGetSymbolAddress((void**)&xz,    g_xz);
    cudaGetSymbolAddress((void**)&dtBC,  g_dtBC);
    cudaGetSymbolAddress((void**)&hA,    g_hA);
    cudaGetSymbolAddress((void**)&xh,    g_xh);
    cudaGetSymbolAddress((void**)&xch,   g_xch);
    cudaGetSymbolAddress((void**)&yh,    g_yh);
    cudaGetSymbolAddress((void**)&Wih,   g_Wih);
    cudaGetSymbolAddress((void**)&Wcat,  g_Wcat);
    cudaGetSymbolAddress((void**)&Woh,   g_Woh);
    cudaGetSymbolAddress((void**)&Aprod, g_Aprod);
    cudaGetSymbolAddress((void**)&Hend,  g_Hend);
    cudaGetSymbolAddress((void**)&Carry, g_Carry);

    cudaFuncSetAttribute(gemm_fp16<__half>,
                         cudaFuncAttributeMaxDynamicSharedMemorySize, GEMM_SMEM);
    cudaFuncSetAttribute(gemm_fp16<float>,
                         cudaFuncAttributeMaxDynamicSharedMemorySize, GEMM_SMEM);

    const int M = MTOT;

    // 0) fp16 conversion of all GEMM operands in ONE launch
    {
        SegTable st;
        size_t n0 = (size_t)M * DM;        // x
        size_t n1 = (size_t)2 * DI * DM;   // Wi
        size_t n2 = (size_t)DI * DI;       // Wdt
        size_t n3 = (size_t)DI * DI;       // WB
        size_t n4 = (size_t)DI * DI;       // WC
        size_t n5 = (size_t)DM * DI;       // Wo
        st.src[0] = x;    st.dst[0] = xh;
        st.src[1] = Wi;   st.dst[1] = Wih;
        st.src[2] = Wdt;  st.dst[2] = Wcat;
        st.src[3] = WB;   st.dst[3] = Wcat + n2;
        st.src[4] = WC;   st.dst[4] = Wcat + 2 * n2;
        st.src[5] = Wo;   st.dst[5] = Woh;
        st.cum[0] = 0;
        st.cum[1] = st.cum[0] + n0;
        st.cum[2] = st.cum[1] + n1;
        st.cum[3] = st.cum[2] + n2;
        st.cum[4] = st.cum[3] + n3;
        st.cum[5] = st.cum[4] + n4;
        st.cum[6] = st.cum[5] + n5;
        unsigned blocks = (unsigned)((st.cum[6] / 8 + 255) / 256);
        to_half_multi<<<blocks, 256>>>(st);
    }

    // 1) in_proj: xz[M, 4096] (fp16) = xh @ Wih^T
    gemm_fp16<__half><<<dim3((2 * DI) / BN, M / BM), NTHR, GEMM_SMEM>>>(
        xh, Wih, xz, DM, 2 * DI);

    // 2) depthwise causal conv + SiLU -> xch (fp16)
    conv_silu_kernel<<<(unsigned)(((size_t)M * DI) / 256), 256>>>(xz, Wconv, bconv, xch);

    // 3) fused dt|B|C projection: dtBC[M, 6144] (fp16) = xch @ Wcat^T
    gemm_fp16<__half><<<dim3(N3 / BN, M / BM), NTHR, GEMM_SMEM>>>(
        xch, Wcat, dtBC, DI, N3);

    // 4) chunked scan: pass1 stores (h_local, Aprefix); tiny carry pass;
    //    pass3 fully elementwise
    scan_chunks<<<(BB * NCHUNK * DI) / 256, 256>>>(xch, dtBC, bdt, A_log,
                                                   hA, Aprod, Hend);
    scan_carry <<<(BB * DI) / 256, 256>>>(Aprod, Hend, Carry);
    scan_out   <<<(unsigned)(((size_t)M * DI) / 256), 256>>>(xz, dtBC, hA,
                                                             Carry, yh);

    // 5) out_proj (fp32 out, final result)
    gemm_fp16<float><<<dim3(DM / BN, M / BM), NTHR, GEMM_SMEM>>>(
        yh, Woh, out, DI, DM);
}